// round 8
// baseline (speedup 1.0000x reference)
#include <cuda_runtime.h>
#include <cstdint>

typedef unsigned long long u64;

#define VOCAB   10000
#define EMB     256
#define UNITS   128
#define NG      512        // 4 * UNITS, gate order i,f,c,o
#define BATCH   256
#define SEQ     1024

// Wr k-split: rows [0,KR) in registers, [KR,128) in shared memory
#define KR      64
#define KRP     32         // KR/2 f32x2 pairs (register weights per thread)
#define KS      64
#define KS4     16         // KS/4 (smem weight ulonglong2 entries per thread)

#define NTHREADS 512
#define NBLOCKS  128       // 2 batch rows per block, one wave

// Precomputed gate table: G[v][c] = sum_e emb[v][e]*Wk[e][c] + b[c]  (20.5 MB)
__device__ float g_G[VOCAB * NG];

// ---------------- f32x2 helpers ----------------
__device__ __forceinline__ u64 fma2(u64 a, u64 b, u64 c) {
    u64 d;
    asm("fma.rn.f32x2 %0, %1, %2, %3;" : "=l"(d) : "l"(a), "l"(b), "l"(c));
    return d;
}
__device__ __forceinline__ u64 pk2(float x, float y) {
    u64 r;
    asm("mov.b64 %0, {%1, %2};" : "=l"(r) : "f"(x), "f"(y));
    return r;
}
__device__ __forceinline__ float2 upk2(u64 v) {
    float2 r;
    asm("mov.b64 {%0, %1}, %2;" : "=f"(r.x), "=f"(r.y) : "l"(v));
    return r;
}
__device__ __forceinline__ float sigmoidf(float x) {
    return __fdividef(1.0f, 1.0f + __expf(-x));
}

// ---------------- Kernel 1: G = emb @ Wk + b ----------------
#define VB 16
__global__ void __launch_bounds__(512)
gbuild_kernel(const float* __restrict__ emb, const float* __restrict__ Wk,
              const float* __restrict__ b)
{
    __shared__ float es[VB][EMB];
    const int c  = threadIdx.x;
    const int v0 = blockIdx.x * VB;

    for (int i = c; i < VB * EMB; i += 512)
        es[i / EMB][i % EMB] = emb[v0 * EMB + i];
    __syncthreads();

    float acc[VB];
#pragma unroll
    for (int v = 0; v < VB; v++) acc[v] = 0.0f;

    for (int e = 0; e < EMB; e += 4) {
        const float w0 = Wk[(e + 0) * NG + c];
        const float w1 = Wk[(e + 1) * NG + c];
        const float w2 = Wk[(e + 2) * NG + c];
        const float w3 = Wk[(e + 3) * NG + c];
#pragma unroll
        for (int v = 0; v < VB; v++) {
            float4 ev = *(const float4*)&es[v][e];
            acc[v] += ev.x * w0 + ev.y * w1 + ev.z * w2 + ev.w * w3;
        }
    }
    const float bc = b[c];
#pragma unroll
    for (int v = 0; v < VB; v++)
        g_G[(v0 + v) * NG + c] = acc[v] + bc;
}

// ---------------- Kernel 2: persistent LSTM recurrence ----------------
// 128 CTAs x 512 threads (16 warps -> 4/SMSP), 2 batch rows per CTA.
// Thread j: u = j>>2, q = j&3. Owns gate-column c = 128q + u for BOTH
// rows (z_r0, z_r1). Lanes 4u+q hold gate q of unit u; a 2-round shfl
// butterfly (xor 1 then xor 2) leaves lane 4u+0 with all 4 gates of
// (u,row0) and lane 4u+1 with (u,row1); those lanes carry c_state and
// store h. One __syncthreads per step (double-buffered h).
//
// h interleaved by k-pairs, double-buffered:
//   hbuf[buf][kk] = float4 { r0[2kk], r0[2kk+1], r1[2kk], r1[2kk+1] }
// Smem weights (k in [KR,128)): Wsm[kk2][j] = ulonglong2 of the thread's
// k-pairs {KR+4kk2,..+1} and {..+2,..+3} -> per-lane 16B, conflict-free.
#define WS_BYTES (KS4 * NTHREADS * 16)   // 131072 B
#define HB_OFF   WS_BYTES                // 2 bufs x 128 u64 = 2048 B
#define XS_OFF   (HB_OFF + 2048)
#define SMEM_TOTAL (XS_OFF + 2 * SEQ * 4)

__global__ void __launch_bounds__(NTHREADS, 1)
lstm_kernel(const int* __restrict__ x, const float* __restrict__ Wr,
            const float* __restrict__ Wd, const float* __restrict__ bd,
            float* __restrict__ out)
{
    extern __shared__ char smem[];
    ulonglong2* Wsm = (ulonglong2*)smem;            // [KS4][512]
    u64*       hbuf = (u64*)(smem + HB_OFF);        // [2][128] u64
    int*       xs   = (int*)(smem + XS_OFF);

    const int j   = threadIdx.x;
    const int blk = blockIdx.x;
    const int u   = j >> 2;
    const int q   = j & 3;
    const int c   = 128 * q + u;          // my gate-column

    // ---- one-time setup ----
    for (int i = j; i < 2 * SEQ; i += NTHREADS) {
        int row = i >> 10, tt = i & (SEQ - 1);
        xs[i] = x[(blk * 2 + row) * SEQ + tt];
    }
    // register weights: k in [0,KR), pair kk = k-rows {2kk, 2kk+1}
    u64 w[KRP];
#pragma unroll
    for (int kk = 0; kk < KRP; kk++)
        w[kk] = pk2(Wr[(2 * kk) * NG + c], Wr[(2 * kk + 1) * NG + c]);
    // smem weights: k in [KR,128)
#pragma unroll
    for (int kk2 = 0; kk2 < KS4; kk2++) {
        const int k = KR + 4 * kk2;
        ulonglong2 wv;
        wv.x = pk2(Wr[(k + 0) * NG + c], Wr[(k + 1) * NG + c]);
        wv.y = pk2(Wr[(k + 2) * NG + c], Wr[(k + 3) * NG + c]);
        Wsm[kk2 * NTHREADS + j] = wv;
    }
    // zero both h buffers
    for (int i = j; i < 256; i += NTHREADS) hbuf[i] = 0ull;
    __syncthreads();

    const int r = q & 1;                  // my gate-phase row (q<2 canonical)
    float c_state = 0.0f;

    for (int t = 0; t < SEQ; t++) {
        const u64* hc = hbuf + ((t & 1) << 7);       // current h, 128 u64

        // prefetch gate-table gathers for (unit u, row r)
        const int tok = xs[r * SEQ + t];
        const float* gr = g_G + (size_t)tok * NG + u;
        const float xg0 = gr[0];
        const float xg1 = gr[128];
        const float xg2 = gr[256];
        const float xg3 = gr[384];

        // ---- FMA phase: z for column c, both rows ----
        u64 a0 = 0ull, a1 = 0ull;                    // row0, row1
#pragma unroll
        for (int kk = 0; kk < KRP; kk++) {
            ulonglong2 hv = *(const ulonglong2*)(hc + 2 * kk);  // .x r0, .y r1
            a0 = fma2(w[kk], hv.x, a0);
            a1 = fma2(w[kk], hv.y, a1);
        }
#pragma unroll
        for (int kk2 = 0; kk2 < KS4; kk2++) {
            ulonglong2 wv  = Wsm[kk2 * NTHREADS + j];
            ulonglong2 hva = *(const ulonglong2*)(hc + 2 * (KRP + 2 * kk2));
            ulonglong2 hvb = *(const ulonglong2*)(hc + 2 * (KRP + 2 * kk2 + 1));
            a0 = fma2(wv.x, hva.x, a0);
            a1 = fma2(wv.x, hva.y, a1);
            a0 = fma2(wv.y, hvb.x, a0);
            a1 = fma2(wv.y, hvb.y, a1);
        }
        float2 s;
        s = upk2(a0); const float z0 = s.x + s.y;    // (gate q, row 0)
        s = upk2(a1); const float z1 = s.x + s.y;    // (gate q, row 1)

        // ---- shfl butterfly across the 4-lane unit group ----
        // xor1: thread ends with gates {q&~1, q|1} for row q&1
        const float t0 = __shfl_xor_sync(0xffffffffu, z0, 1);
        const float t1 = __shfl_xor_sync(0xffffffffu, z1, 1);
        const float a_low  = (q & 1) ? t1 : z0;      // gate q&~1, row r
        const float a_high = (q & 1) ? z1 : t0;      // gate q|1,  row r
        // xor2: pick up the other gate pair (same row parity)
        const float b_low  = __shfl_xor_sync(0xffffffffu, a_low, 2);
        const float b_high = __shfl_xor_sync(0xffffffffu, a_high, 2);
        // q<2: a=(g0,g1), b=(g2,g3). q>=2: swapped (duplicate compute).
        const float zi = ((q & 2) ? b_low  : a_low)  + xg0;
        const float zf = ((q & 2) ? b_high : a_high) + xg1;
        const float zc = ((q & 2) ? a_low  : b_low)  + xg2;
        const float zo = ((q & 2) ? a_high : b_high) + xg3;

        const float ig = sigmoidf(zi);
        const float fg = sigmoidf(zf);
        const float gg = fmaxf(zc, 0.0f);            // activation = relu
        const float og = sigmoidf(zo);
        c_state = fg * c_state + ig * gg;
        const float hn = og * fmaxf(c_state, 0.0f);

        // lanes q<2 store h(t+1) for (u, row r) into the other buffer:
        // float word index = (u>>1)*4 + 2r + (u&1)
        if (q < 2) {
            float* hnx = (float*)(hbuf + (((t + 1) & 1) << 7));
            hnx[(u >> 1) * 4 + 2 * r + (u & 1)] = hn;
        }
        __syncthreads();
    }

    // ---- dense head: final h lives in buffer 0 (SEQ is even) ----
    if (j < 4) {
        const int rr = j >> 1, oc = j & 1;
        const float* hb = (const float*)hbuf;        // buffer 0
        float acc = bd[oc];
        for (int uu = 0; uu < UNITS; uu++)
            acc += hb[(uu >> 1) * 4 + 2 * rr + (uu & 1)] * Wd[uu * 2 + oc];
        out[(blk * 2 + rr) * 2 + oc] = acc;
    }
}

// ---------------- launch ----------------
extern "C" void kernel_launch(void* const* d_in, const int* in_sizes, int n_in,
                              void* d_out, int out_size)
{
    const int*   x   = 0;
    const float *emb = 0, *Wk = 0, *Wr = 0, *bb = 0, *Wd = 0, *bd = 0;
    for (int i = 0; i < n_in; i++) {
        switch (in_sizes[i]) {                       // all sizes are distinct
            case BATCH * SEQ: x   = (const int*)  d_in[i]; break;  // 262144
            case VOCAB * EMB: emb = (const float*)d_in[i]; break;  // 2560000
            case EMB * NG:    Wk  = (const float*)d_in[i]; break;  // 131072
            case UNITS * NG:  Wr  = (const float*)d_in[i]; break;  // 65536
            case NG:          bb  = (const float*)d_in[i]; break;  // 512
            case UNITS * 2:   Wd  = (const float*)d_in[i]; break;  // 256
            case 2:           bd  = (const float*)d_in[i]; break;
        }
    }

    gbuild_kernel<<<VOCAB / VB, 512>>>(emb, Wk, bb);

    cudaFuncSetAttribute(lstm_kernel,
                         cudaFuncAttributeMaxDynamicSharedMemorySize, SMEM_TOTAL);
    lstm_kernel<<<NBLOCKS, NTHREADS, SMEM_TOTAL>>>(x, Wr, Wd, bd, (float*)d_out);
}

// round 9
// speedup vs baseline: 1.6431x; 1.6431x over previous
#include <cuda_runtime.h>
#include <cstdint>

typedef unsigned long long u64;

#define VOCAB   10000
#define EMB     256
#define UNITS   128
#define NG      512        // 4 * UNITS, gate order i,f,c,o
#define BATCH   256
#define SEQ     1024

// Wr k-split: rows [0,KR) in registers, [KR,128) in shared memory
#define KR      80
#define KRP     40         // KR/2 f32x2 pairs
#define KS      48
#define KSP     24         // KS/2

#define NTHREADS 256
#define NBLOCKS  128       // 2 batch rows per block, one wave

// Precomputed gate table: G[v][c] = sum_e emb[v][e]*Wk[e][c] + b[c]  (20.5 MB)
__device__ float g_G[VOCAB * NG];

// ---------------- f32x2 helpers ----------------
__device__ __forceinline__ u64 fma2(u64 a, u64 b, u64 c) {
    u64 d;
    asm("fma.rn.f32x2 %0, %1, %2, %3;" : "=l"(d) : "l"(a), "l"(b), "l"(c));
    return d;
}
__device__ __forceinline__ u64 pk2(float x, float y) {
    u64 r;
    asm("mov.b64 %0, {%1, %2};" : "=l"(r) : "f"(x), "f"(y));
    return r;
}
__device__ __forceinline__ float2 upk2(u64 v) {
    float2 r;
    asm("mov.b64 {%0, %1}, %2;" : "=f"(r.x), "=f"(r.y) : "l"(v));
    return r;
}
__device__ __forceinline__ float sigmoidf(float x) {
    return __fdividef(1.0f, 1.0f + __expf(-x));
}

// ---------------- Kernel 1: G = emb @ Wk + b ----------------
#define VB 16
__global__ void __launch_bounds__(512)
gbuild_kernel(const float* __restrict__ emb, const float* __restrict__ Wk,
              const float* __restrict__ b)
{
    __shared__ float es[VB][EMB];
    const int c  = threadIdx.x;
    const int v0 = blockIdx.x * VB;

    for (int i = c; i < VB * EMB; i += 512)
        es[i / EMB][i % EMB] = emb[v0 * EMB + i];
    __syncthreads();

    float acc[VB];
#pragma unroll
    for (int v = 0; v < VB; v++) acc[v] = 0.0f;

    for (int e = 0; e < EMB; e += 4) {
        const float w0 = Wk[(e + 0) * NG + c];
        const float w1 = Wk[(e + 1) * NG + c];
        const float w2 = Wk[(e + 2) * NG + c];
        const float w3 = Wk[(e + 3) * NG + c];
#pragma unroll
        for (int v = 0; v < VB; v++) {
            float4 ev = *(const float4*)&es[v][e];
            acc[v] += ev.x * w0 + ev.y * w1 + ev.z * w2 + ev.w * w3;
        }
    }
    const float bc = b[c];
#pragma unroll
    for (int v = 0; v < VB; v++)
        g_G[(v0 + v) * NG + c] = acc[v] + bc;
}

// ---------------- Kernel 2: persistent LSTM recurrence ----------------
// R7 structure (2 rows/CTA, 256 thr, thread j: u=j>>1, p=j&1 owning gate
// cols 128p+u and 128(p+2)+u; shfl.xor(1) gate exchange; double-buffered
// interleaved h; one __syncthreads/step) PLUS phase staggering:
// warps 0-3 run REG-weights then SMEM-weights; warps 4-7 (their SMSP
// partners) run SMEM then REG, so each SMSP always has one FMA-heavy and
// one LSU-heavy warp in flight -> L1 crossbar and FMA pipe overlap.
#define WS_BYTES (KSP * NTHREADS * 16)   // 98304 B
#define HB_OFF   WS_BYTES                // 2 bufs x 128 u64 = 2048 B
#define XS_OFF   (HB_OFF + 2048)
#define SMEM_TOTAL (XS_OFF + 2 * SEQ * 4)

__global__ void __launch_bounds__(NTHREADS, 1)
lstm_kernel(const int* __restrict__ x, const float* __restrict__ Wr,
            const float* __restrict__ Wd, const float* __restrict__ bd,
            float* __restrict__ out)
{
    extern __shared__ char smem[];
    ulonglong2* W2  = (ulonglong2*)smem;            // [KSP][256]
    u64*       hbuf = (u64*)(smem + HB_OFF);        // [2][128] u64
    int*       xs   = (int*)(smem + XS_OFF);

    const int j   = threadIdx.x;
    const int blk = blockIdx.x;
    const int u   = j >> 1;
    const int p   = j & 1;
    const int cA  = 128 * p + u;          // gate p
    const int cB  = 128 * (p + 2) + u;    // gate p+2
    const bool smemFirst = (j >= 128);    // warps 4-7: SMEM section first

    // ---- one-time setup ----
    for (int i = j; i < 2 * SEQ; i += NTHREADS) {
        int row = i >> 10, tt = i & (SEQ - 1);
        xs[i] = x[(blk * 2 + row) * SEQ + tt];
    }
    // register weights: k in [0,KR), pair kk = k-rows {2kk, 2kk+1}
    u64 w0[KRP], w1[KRP];
#pragma unroll
    for (int kk = 0; kk < KRP; kk++) {
        w0[kk] = pk2(Wr[(2 * kk) * NG + cA], Wr[(2 * kk + 1) * NG + cA]);
        w1[kk] = pk2(Wr[(2 * kk) * NG + cB], Wr[(2 * kk + 1) * NG + cB]);
    }
    // smem weights: k in [KR,128), per-thread contiguous 16B
    for (int kk = 0; kk < KSP; kk++) {
        const int k = KR + 2 * kk;
        ulonglong2 wv;
        wv.x = pk2(Wr[k * NG + cA], Wr[(k + 1) * NG + cA]);
        wv.y = pk2(Wr[k * NG + cB], Wr[(k + 1) * NG + cB]);
        W2[kk * NTHREADS + j] = wv;
    }
    // zero both h buffers
    for (int i = j; i < 256; i += NTHREADS) hbuf[i] = 0ull;
    __syncthreads();

    float c_state = 0.0f;

    for (int t = 0; t < SEQ; t++) {
        const u64* hc = hbuf + ((t & 1) << 7);       // current h, 128 u64

        // prefetch gate-table gathers for (unit u, row p)
        const int tok = xs[p * SEQ + t];
        const float* gr = g_G + (size_t)tok * NG + u;
        const float xg0 = gr[0];
        const float xg1 = gr[128];
        const float xg2 = gr[256];
        const float xg3 = gr[384];

        // ---- FMA phase: z for cols cA,cB over both rows (staggered) ----
        u64 aA0 = 0ull, aA1 = 0ull, aB0 = 0ull, aB1 = 0ull;

#define REG_SECTION()                                                   \
        _Pragma("unroll")                                               \
        for (int kk = 0; kk < KRP; kk++) {                              \
            ulonglong2 hv = *(const ulonglong2*)(hc + 2 * kk);          \
            aA0 = fma2(w0[kk], hv.x, aA0);                              \
            aA1 = fma2(w0[kk], hv.y, aA1);                              \
            aB0 = fma2(w1[kk], hv.x, aB0);                              \
            aB1 = fma2(w1[kk], hv.y, aB1);                              \
        }
#define SMEM_SECTION()                                                  \
        _Pragma("unroll")                                               \
        for (int kk = 0; kk < KSP; kk++) {                              \
            ulonglong2 hv = *(const ulonglong2*)(hc + 2 * (KRP + kk));  \
            ulonglong2 wv = W2[kk * NTHREADS + j];                      \
            aA0 = fma2(wv.x, hv.x, aA0);                                \
            aA1 = fma2(wv.x, hv.y, aA1);                                \
            aB0 = fma2(wv.y, hv.x, aB0);                                \
            aB1 = fma2(wv.y, hv.y, aB1);                                \
        }

        if (smemFirst) {
            SMEM_SECTION();
            REG_SECTION();
        } else {
            REG_SECTION();
            SMEM_SECTION();
        }
#undef REG_SECTION
#undef SMEM_SECTION

        float2 s;
        s = upk2(aA0); const float zA0 = s.x + s.y;   // gate p,   row 0
        s = upk2(aA1); const float zA1 = s.x + s.y;   // gate p,   row 1
        s = upk2(aB0); const float zB0 = s.x + s.y;   // gate p+2, row 0
        s = upk2(aB1); const float zB1 = s.x + s.y;   // gate p+2, row 1

        // ---- lane-pair exchange: collect all 4 gates for row p ----
        const float r1 = __shfl_xor_sync(0xffffffffu, p ? zA0 : zA1, 1);
        const float r2 = __shfl_xor_sync(0xffffffffu, p ? zB0 : zB1, 1);
        // even (p=0, row0): zi=zA0 zf=r1 zc=zB0 zo=r2
        // odd  (p=1, row1): zi=r1 zf=zA1 zc=r2 zo=zB1
        const float zi = (p ? r1  : zA0) + xg0;
        const float zf = (p ? zA1 : r1)  + xg1;
        const float zc = (p ? r2  : zB0) + xg2;
        const float zo = (p ? zB1 : r2)  + xg3;

        const float ig = sigmoidf(zi);
        const float fg = sigmoidf(zf);
        const float gg = fmaxf(zc, 0.0f);     // activation = relu
        const float og = sigmoidf(zo);
        c_state = fg * c_state + ig * gg;
        const float hn = og * fmaxf(c_state, 0.0f);

        // write h(t+1) into the other buffer, interleaved layout:
        // float word index = (u>>1)*4 + 2p + (u&1)
        float* hnx = (float*)(hbuf + (((t + 1) & 1) << 7));
        hnx[(u >> 1) * 4 + 2 * p + (u & 1)] = hn;
        __syncthreads();
    }

    // ---- dense head: final h lives in buffer 0 (SEQ is even) ----
    if (j < 4) {
        const int rr = j >> 1, oc = j & 1;
        const float* hb = (const float*)hbuf;      // buffer 0
        float acc = bd[oc];
        for (int uu = 0; uu < UNITS; uu++)
            acc += hb[(uu >> 1) * 4 + 2 * rr + (uu & 1)] * Wd[uu * 2 + oc];
        out[(blk * 2 + rr) * 2 + oc] = acc;
    }
}

// ---------------- launch ----------------
extern "C" void kernel_launch(void* const* d_in, const int* in_sizes, int n_in,
                              void* d_out, int out_size)
{
    const int*   x   = 0;
    const float *emb = 0, *Wk = 0, *Wr = 0, *bb = 0, *Wd = 0, *bd = 0;
    for (int i = 0; i < n_in; i++) {
        switch (in_sizes[i]) {                       // all sizes are distinct
            case BATCH * SEQ: x   = (const int*)  d_in[i]; break;  // 262144
            case VOCAB * EMB: emb = (const float*)d_in[i]; break;  // 2560000
            case EMB * NG:    Wk  = (const float*)d_in[i]; break;  // 131072
            case UNITS * NG:  Wr  = (const float*)d_in[i]; break;  // 65536
            case NG:          bb  = (const float*)d_in[i]; break;  // 512
            case UNITS * 2:   Wd  = (const float*)d_in[i]; break;  // 256
            case 2:           bd  = (const float*)d_in[i]; break;
        }
    }

    gbuild_kernel<<<VOCAB / VB, 512>>>(emb, Wk, bb);

    cudaFuncSetAttribute(lstm_kernel,
                         cudaFuncAttributeMaxDynamicSharedMemorySize, SMEM_TOTAL);
    lstm_kernel<<<NBLOCKS, NTHREADS, SMEM_TOTAL>>>(x, Wr, Wd, bd, (float*)d_out);
}